// round 4
// baseline (speedup 1.0000x reference)
#include <cuda_runtime.h>
#include <math.h>

// DTW loss, LEN=2048, squared-difference cost, output = sqrt(DTW[N-1][N-1]).
//
// Uniform recurrence with virtual border row/col = +inf and corner (−1,−1) = 0:
//   v[i][j] = c(i,j) + min(v[i-1][j], v[i][j-1], v[i-1][j-1])
// reproduces the reference exactly (row 0 = cumsum, col 0 = up-only).
//
// Systolic schedule: thread t owns columns [8t, 8t+8); at step s it processes
// row r = s - t. It needs from thread t-1 only that thread's last-column value
// for rows r (left) and r-1 (diag) — passed one step late via __shfl_up within
// a warp and via a parity double-buffered smem slot across warp boundaries.
// One __syncthreads per step; 2048+255 = 2303 steps.

#define LEN   2048
#define NT    256
#define CPT   8                 // columns per thread
#define NWARP (NT / 32)
#define STEPS (LEN + NT - 1)

__global__ __launch_bounds__(NT, 1)
void dtw_systolic_kernel(const float* __restrict__ x,
                         const float* __restrict__ y,
                         float* __restrict__ out)
{
    __shared__ float xs[LEN];
    __shared__ float bbuf[2][NWARP];   // parity-double-buffered warp-boundary handoff

    const int tid  = threadIdx.x;
    const int lane = tid & 31;
    const int wid  = tid >> 5;
    const float INF = __int_as_float(0x7f800000);

    // Preload x into smem (read once per row per thread, lane-varying index).
    for (int i = tid; i < LEN; i += NT) xs[i] = x[i];
    if (tid < 2 * NWARP) ((float*)bbuf)[tid] = INF;

    // Per-thread column data in registers: -(y_j) and previous-row values.
    float negY[CPT];
    float up[CPT];
#pragma unroll
    for (int j = 0; j < CPT; ++j) {
        negY[j] = -y[tid * CPT + j];
        up[j]   = INF;                 // virtual row -1
    }

    // Incoming boundary values for the upcoming row:
    //   leftIn = neighbor's last column at row r   (v[r][8t-1])
    //   diagIn = neighbor's last column at row r-1 (v[r-1][8t-1])
    // Thread 0: left is the virtual column (-1) = INF; diag at row 0 is the
    // corner = 0, INF afterwards (falls out of the update automatically).
    float leftIn = INF;
    float diagIn = (tid == 0) ? 0.0f : INF;

    __syncthreads();

    for (int s = 0; s < STEPS; ++s) {
        const int r = s - tid;
        float pub = INF;                       // inactive threads publish INF (virtual rows)
        if ((unsigned)r < (unsigned)LEN) {
            const float xi = xs[r];
            float left = leftIn;
            float dg   = diagIn;               // up_{j-1} for the first cell
#pragma unroll
            for (int j = 0; j < CPT; ++j) {
                const float d  = xi + negY[j];         // FADD (fma pipe)
                const float uj = up[j];
                const float m  = fminf(uj, dg);        // FMNMX (alu pipe), off-chain
                const float t  = fmaf(d, d, left);     // FFMA, on serial chain
                const float a  = fmaf(d, d, m);        // FFMA, off-chain
                const float v  = fminf(a, t);          // FMNMX, on chain
                up[j] = v;
                left  = v;
                dg    = uj;                            // old up_j becomes diag source
            }
            pub = left;                        // last-column value of row r
        }

        // Hand the boundary value to thread tid+1 for its next step.
        float newLeft = __shfl_up_sync(0xFFFFFFFFu, pub, 1);
        const int par = s & 1;
        if (lane == 31) bbuf[par][wid] = pub;
        __syncthreads();
        if (lane == 0) newLeft = (wid == 0) ? INF : bbuf[par][wid - 1];

        diagIn = leftIn;    // neighbor row r   becomes diag for row r+1
        leftIn = newLeft;   // neighbor row r+1 becomes left for row r+1
    }

    // Thread NT-1 processed row LEN-1 on the final step; up[CPT-1] = v[2047][2047].
    if (tid == NT - 1) out[0] = sqrtf(up[CPT - 1]);
}

extern "C" void kernel_launch(void* const* d_in, const int* in_sizes, int n_in,
                              void* d_out, int out_size)
{
    (void)in_sizes; (void)n_in; (void)out_size;
    const float* x = (const float*)d_in[0];
    const float* y = (const float*)d_in[1];
    float* out = (float*)d_out;
    dtw_systolic_kernel<<<1, NT>>>(x, y, out);
}

// round 5
// speedup vs baseline: 1.7843x; 1.7843x over previous
#include <cuda_runtime.h>
#include <math.h>

// DTW loss, LEN=2048, squared-difference cost, out = sqrt(DTW[N-1][N-1]).
//
// Recurrence (virtual border = +inf, corner(-1,-1) = 0):
//   v[i][j] = (x_i - y_j)^2 + min(v[i-1][j], v[i][j-1], v[i-1][j-1])
//
// Systolic, row-blocked: thread t owns columns [8t, 8t+8); at step s it
// processes row block b = s - t, i.e. rows [4b, 4b+4). Per step it needs the
// neighbor's last-column values for those 4 rows (float4 via parity
// double-buffered smem) plus one saved diag. 4 ops/cell:
//   d = xi + (-y_j); m = fmin(up, dg); mm = fmin(m, left); v = fma(d,d,mm)
// Steps = 2048/4 + 255 = 767, one __syncthreads per step, no shfl.

#define LEN   2048
#define NT    256
#define CPT   8                    // columns per thread
#define RPS   4                    // rows per step
#define NBLK  (LEN / RPS)          // 512 row blocks
#define STEPS (NBLK + NT - 1)      // 767

__global__ __launch_bounds__(NT, 1)
void dtw_systolic_r4_kernel(const float* __restrict__ x,
                            const float* __restrict__ y,
                            float* __restrict__ out)
{
    __shared__ float4 xs4[LEN / 4];     // x, 4 rows per entry (8 KB)
    __shared__ float4 buf[2][NT];       // parity-buffered boundary handoff (8 KB)

    const int tid = threadIdx.x;
    const float INF = __int_as_float(0x7f800000);

    // Preload x.
    for (int i = tid; i < LEN / 4; i += NT)
        xs4[i] = reinterpret_cast<const float4*>(x)[i];

    // Column-strip state in registers.
    float negY[CPT], up[CPT];
#pragma unroll
    for (int j = 0; j < CPT; ++j) {
        negY[j] = -y[tid * CPT + j];
        up[j]   = INF;                   // virtual row -1
    }

    // diag entering the first row of the next block: v[4b-1][8t-1].
    // Thread 0, block 0: the corner (-1,-1) = 0. Otherwise +inf initially.
    float diag = (tid == 0) ? 0.0f : INF;

    __syncthreads();

    for (int s = 0; s < STEPS; ++s) {
        const int b   = s - tid;
        const int par = s & 1;

        // Neighbor's last-column values for my 4 rows (written at step s-1,
        // visible after that step's barrier). Thread 0: virtual column = inf.
        float4 L = (tid == 0) ? make_float4(INF, INF, INF, INF)
                              : buf[par ^ 1][tid - 1];

        if ((unsigned)b < (unsigned)NBLK) {
            const float4 xv = xs4[b];
            const float lx[4] = {L.x, L.y, L.z, L.w};
            const float xr[4] = {xv.x, xv.y, xv.z, xv.w};
            float pb[4];

            float dgen = diag;           // diag entering row 4b
#pragma unroll
            for (int k = 0; k < RPS; ++k) {
                float left = lx[k];
                float dg   = dgen;
                const float xi = xr[k];
#pragma unroll
                for (int j = 0; j < CPT; ++j) {
                    const float d  = xi + negY[j];     // FADD
                    const float m  = fminf(up[j], dg); // off-chain FMNMX
                    const float mm = fminf(m, left);   // chain FMNMX
                    const float v  = fmaf(d, d, mm);   // chain FFMA
                    dg    = up[j];                     // reg rename (free)
                    up[j] = v;
                    left  = v;
                }
                pb[k] = left;            // my last-column value, row 4b+k
                dgen  = lx[k];           // neighbor row 4b+k -> diag for row 4b+k+1
            }
            diag = lx[3];                // diag entering first row of block b+1

            buf[par][tid] = make_float4(pb[0], pb[1], pb[2], pb[3]);
        }
        __syncthreads();
    }

    // Thread NT-1 finished row 2047 on its last active step.
    if (tid == NT - 1) out[0] = sqrtf(up[CPT - 1]);
}

extern "C" void kernel_launch(void* const* d_in, const int* in_sizes, int n_in,
                              void* d_out, int out_size)
{
    (void)in_sizes; (void)n_in; (void)out_size;
    const float* x = (const float*)d_in[0];
    const float* y = (const float*)d_in[1];
    float* out = (float*)d_out;
    dtw_systolic_r4_kernel<<<1, NT>>>(x, y, out);
}

// round 7
// speedup vs baseline: 2.4232x; 1.3581x over previous
#include <cuda_runtime.h>
#include <math.h>

// DTW loss, LEN=2048, squared-difference cost, out = sqrt(DTW[N-1][N-1]).
//
// Bidirectional decomposition: any monotone path crosses row 1023 -> 1024
// exactly once (down or diag), so
//   DTW^2 = min_j ( F[1023][j] + min(B[1024][j], B[1024][j+1]) )
// F = forward DP over rows 0..1023 of (x,y); B = backward DP over rows
// 1024..2047, which equals the forward DP on (reverse(x), reverse(y)):
//   B[1024][j] = G[1023][2047-j].
// Kernel 1 (grid=2): CTA0 computes F row 1023, CTA1 computes G row 1023
// (each a 1024-row systolic DP, RPS=4, 511 steps). Kernel 2 combines.
//
// Per-cell recurrence (virtual border = +inf, corner(-1,-1) = 0):
//   v = (x_i - y_j)^2 + min(up, left, diag)   -> 4 ops:
//   d = xi + (-y_j); m = fmin(up, dg); mm = fmin(m, left); v = fma(d,d,mm)

#define LEN   2048
#define HALF  1024
#define NT    256
#define CPT   8                    // columns per thread
#define RPS   4                    // rows per step
#define NBLK  (HALF / RPS)         // 256 row blocks per half
#define STEPS (NBLK + NT - 1)      // 511

__device__ float g_rows[2][LEN];   // [0]=F row 1023, [1]=G row 1023 (reversed idx)

__global__ __launch_bounds__(NT, 1)
void dtw_half_kernel(const float* __restrict__ x,
                     const float* __restrict__ y)
{
    __shared__ float4 xs4[HALF / 4];    // this half's x rows (4 KB)
    __shared__ float4 buf[2][NT];       // parity-buffered boundary handoff (8 KB)

    const int tid = threadIdx.x;
    const int dir = blockIdx.x;         // 0 = forward half, 1 = reversed half
    const float INF = __int_as_float(0x7f800000);

    // Preload x rows for this half (forward: x[0..1023]; reversed: x[2047..1024]).
    {
        float* xs = reinterpret_cast<float*>(xs4);
        if (dir == 0) {
            for (int i = tid; i < HALF; i += NT) xs[i] = x[i];
        } else {
            for (int i = tid; i < HALF; i += NT) xs[i] = x[LEN - 1 - i];
        }
    }

    // Column-strip state in registers (reversed y for the backward half).
    float negY[CPT], up[CPT];
#pragma unroll
    for (int j = 0; j < CPT; ++j) {
        const int col = tid * CPT + j;
        negY[j] = -((dir == 0) ? y[col] : y[LEN - 1 - col]);
        up[j]   = INF;                   // virtual row -1
    }

    // diag entering the first row of the next block: v[4b-1][8t-1].
    // Thread 0, block 0: the corner (-1,-1) = 0. Otherwise +inf initially.
    float diag = (tid == 0) ? 0.0f : INF;

    __syncthreads();

    for (int s = 0; s < STEPS; ++s) {
        const int b   = s - tid;
        const int par = s & 1;

        // Neighbor's last-column values for my 4 rows (written at step s-1,
        // visible after that step's barrier). Thread 0: virtual column = inf.
        float4 L = (tid == 0) ? make_float4(INF, INF, INF, INF)
                              : buf[par ^ 1][tid - 1];

        if ((unsigned)b < (unsigned)NBLK) {
            const float4 xv = xs4[b];
            const float lx[4] = {L.x, L.y, L.z, L.w};
            const float xr[4] = {xv.x, xv.y, xv.z, xv.w};
            float pb[4];

            float dgen = diag;           // diag entering row 4b
#pragma unroll
            for (int k = 0; k < RPS; ++k) {
                float left = lx[k];
                float dg   = dgen;
                const float xi = xr[k];
#pragma unroll
                for (int j = 0; j < CPT; ++j) {
                    const float d  = xi + negY[j];     // FADD
                    const float m  = fminf(up[j], dg); // off-chain FMNMX
                    const float mm = fminf(m, left);   // chain FMNMX
                    const float v  = fmaf(d, d, mm);   // chain FFMA
                    dg    = up[j];                     // reg rename (free)
                    up[j] = v;
                    left  = v;
                }
                pb[k] = left;            // my last-column value, row 4b+k
                dgen  = lx[k];           // neighbor row 4b+k -> diag for next row
            }
            diag = lx[3];                // diag entering first row of block b+1

            buf[par][tid] = make_float4(pb[0], pb[1], pb[2], pb[3]);
        }
        __syncthreads();
    }

    // Every thread processed all NBLK blocks; up[] = local row HALF-1 values.
#pragma unroll
    for (int j = 0; j < CPT; ++j)
        g_rows[dir][tid * CPT + j] = up[j];
}

__global__ __launch_bounds__(NT, 1)
void dtw_combine_kernel(float* __restrict__ out)
{
    __shared__ float red[NT / 32];
    const int tid = threadIdx.x;
    const float INF = __int_as_float(0x7f800000);

    // term_j = F[1023][j] + min(B[1024][j], B[1024][j+1]),
    // B[1024][j] = g_rows[1][LEN-1-j], B[1024][LEN] = +inf.
    float m = INF;
    for (int j = tid; j < LEN; j += NT) {
        const float F  = g_rows[0][j];
        const float B0 = g_rows[1][LEN - 1 - j];
        const float B1 = (j + 1 < LEN) ? g_rows[1][LEN - 2 - j] : INF;
        m = fminf(m, F + fminf(B0, B1));
    }
#pragma unroll
    for (int o = 16; o; o >>= 1)
        m = fminf(m, __shfl_xor_sync(0xFFFFFFFFu, m, o));
    if ((tid & 31) == 0) red[tid >> 5] = m;
    __syncthreads();
    if (tid < 32) {
        float v = (tid < NT / 32) ? red[tid] : INF;
#pragma unroll
        for (int o = 4; o; o >>= 1)
            v = fminf(v, __shfl_xor_sync(0xFFFFFFFFu, v, o));
        if (tid == 0) out[0] = sqrtf(v);
    }
}

extern "C" void kernel_launch(void* const* d_in, const int* in_sizes, int n_in,
                              void* d_out, int out_size)
{
    (void)in_sizes; (void)n_in; (void)out_size;
    const float* x = (const float*)d_in[0];
    const float* y = (const float*)d_in[1];
    float* out = (float*)d_out;
    dtw_half_kernel<<<2, NT>>>(x, y);
    dtw_combine_kernel<<<1, NT>>>(out);
}

// round 8
// speedup vs baseline: 3.1299x; 1.2917x over previous
#include <cuda_runtime.h>
#include <math.h>

// DTW loss, LEN=2048, squared-difference cost, out = sqrt(DTW[N-1][N-1]).
//
// Bidirectional decomposition (exact): any monotone path crosses row
// 1023 -> 1024 exactly once, so
//   DTW^2 = min_j ( F[1023][j] + min(B[1024][j], B[1024][j+1]) )
// F = forward DP rows 0..1023; B = backward DP rows 1024..2047 = forward DP
// on (reverse(x), reverse(y)):  B[1024][j] = G[1023][2047-j].
//
// One kernel, grid=2: CTA0 computes F, CTA1 computes G. Each is a systolic
// column DP: NT=128 threads, 16 columns/thread, 4 rows/step -> 383 steps
// (256 row blocks + 127 skew). Boundary handoff = one float4 smem slot,
// parity double-buffered, one __syncthreads per step.
// The last CTA to finish fuses the combine (atomic counter + fences).
//
// Per-cell (virtual border = +inf, corner(-1,-1) = 0):
//   d = xi + (-y_j); m = fmin(up, dg); mm = fmin(m, left); v = fma(d,d,mm)

#define LEN   2048
#define HALF  1024
#define NT    128
#define CPT   16                   // columns per thread
#define RPS   4                    // rows per step
#define NBLK  (HALF / RPS)         // 256
#define STEPS (NBLK + NT - 1)      // 383

__device__ float g_rows[2][LEN];   // [0]=F row 1023, [1]=G row 1023 (reversed idx)
__device__ int   g_ctr = 0;        // completion counter (reset each launch)

__global__ __launch_bounds__(NT, 1)
void dtw_fused_kernel(const float* __restrict__ x,
                      const float* __restrict__ y,
                      float* __restrict__ out)
{
    __shared__ float4 xs4[HALF / 4];    // this half's x rows (4 KB)
    __shared__ float4 buf[2][NT];       // parity-buffered boundary handoff (4 KB)
    __shared__ float  red[NT / 32];
    __shared__ int    amLast;

    const int tid = threadIdx.x;
    const int dir = blockIdx.x;         // 0 = forward half, 1 = reversed half
    const float INF = __int_as_float(0x7f800000);

    // Preload x rows for this half (forward: x[0..1023]; reversed: x[2047..1024]).
    {
        float* xs = reinterpret_cast<float*>(xs4);
        if (dir == 0) {
            for (int i = tid; i < HALF; i += NT) xs[i] = x[i];
        } else {
            for (int i = tid; i < HALF; i += NT) xs[i] = x[LEN - 1 - i];
        }
    }

    // Column-strip state in registers (reversed y for the backward half).
    float negY[CPT], up[CPT];
#pragma unroll
    for (int j = 0; j < CPT; ++j) {
        const int col = tid * CPT + j;
        negY[j] = -((dir == 0) ? y[col] : y[LEN - 1 - col]);
        up[j]   = INF;                   // virtual row -1
    }

    // diag entering first row of the next block: v[4b-1][16t-1].
    // Thread 0, block 0: corner (-1,-1) = 0. Otherwise +inf initially.
    float diag = (tid == 0) ? 0.0f : INF;

    __syncthreads();

    for (int s = 0; s < STEPS; ++s) {
        const int b   = s - tid;
        const int par = s & 1;

        // Neighbor's last-column values for my 4 rows (written at step s-1,
        // visible after that step's barrier). Thread 0: virtual column = inf.
        float4 L = (tid == 0) ? make_float4(INF, INF, INF, INF)
                              : buf[par ^ 1][tid - 1];

        if ((unsigned)b < (unsigned)NBLK) {
            const float4 xv = xs4[b];
            const float lx[4] = {L.x, L.y, L.z, L.w};
            const float xr[4] = {xv.x, xv.y, xv.z, xv.w};
            float pb[4];

            float dgen = diag;           // diag entering row 4b
#pragma unroll
            for (int k = 0; k < RPS; ++k) {
                float left = lx[k];
                float dg   = dgen;
                const float xi = xr[k];
#pragma unroll
                for (int j = 0; j < CPT; ++j) {
                    const float d  = xi + negY[j];     // FADD
                    const float m  = fminf(up[j], dg); // off-chain FMNMX
                    const float mm = fminf(m, left);   // chain FMNMX
                    const float v  = fmaf(d, d, mm);   // chain FFMA
                    dg    = up[j];                     // reg rename (free)
                    up[j] = v;
                    left  = v;
                }
                pb[k] = left;            // my last-column value, row 4b+k
                dgen  = lx[k];           // neighbor row 4b+k -> diag next row
            }
            diag = lx[3];                // diag entering first row of block b+1

            buf[par][tid] = make_float4(pb[0], pb[1], pb[2], pb[3]);
        }
        __syncthreads();
    }

    // Publish my half's final row (local row HALF-1).
#pragma unroll
    for (int j = 0; j < CPT; ++j)
        g_rows[dir][tid * CPT + j] = up[j];

    // ── fused combine: last CTA to finish does the min-plus join ──
    __threadfence();                     // release g_rows writes
    if (tid == 0) {
        int old = atomicAdd(&g_ctr, 1);
        amLast = (old == 1);
    }
    __syncthreads();
    if (!amLast) return;
    __threadfence();                     // acquire: order reads after atomic

    // term_j = F[1023][j] + min(B[1024][j], B[1024][j+1]),
    // B[1024][j] = g_rows[1][LEN-1-j], B[1024][LEN] = +inf.
    float m = INF;
#pragma unroll
    for (int k = 0; k < LEN / NT; ++k) {
        const int j = tid + k * NT;
        const float F  = g_rows[0][j];
        const float B0 = g_rows[1][LEN - 1 - j];
        const float B1 = (j + 1 < LEN) ? g_rows[1][LEN - 2 - j] : INF;
        m = fminf(m, F + fminf(B0, B1));
    }
#pragma unroll
    for (int o = 16; o; o >>= 1)
        m = fminf(m, __shfl_xor_sync(0xFFFFFFFFu, m, o));
    if ((tid & 31) == 0) red[tid >> 5] = m;
    __syncthreads();
    if (tid == 0) {
        float v = fminf(fminf(red[0], red[1]), fminf(red[2], red[3]));
        out[0] = sqrtf(v);
        g_ctr  = 0;                      // reset for next graph replay
    }
}

extern "C" void kernel_launch(void* const* d_in, const int* in_sizes, int n_in,
                              void* d_out, int out_size)
{
    (void)in_sizes; (void)n_in; (void)out_size;
    const float* x = (const float*)d_in[0];
    const float* y = (const float*)d_in[1];
    float* out = (float*)d_out;
    dtw_fused_kernel<<<2, NT>>>(x, y, out);
}